// round 4
// baseline (speedup 1.0000x reference)
#include <cuda_runtime.h>

typedef unsigned long long ULL;

// ---------------- scratch (static device globals; no allocation) ----------------
static __device__ float g_gi[500 * 1024 * 300];     // 614.4 MB: gi for current layer
static __device__ float g_buf0[500 * 1024 * 100];   // 204.8 MB: e0 / d0 sequence
static __device__ float g_d1[80 * 1024 * 100];      // decoder layer-1 outputs
static __device__ float g_decin[80 * 1024 * 26];    // embedded decoder inputs
static __device__ float g_h0[1024 * 100];           // h_enc0
static __device__ float g_h1[1024 * 100];           // h_enc1

// ---------------- f32x2 helpers ----------------
__device__ __forceinline__ ULL pack2(float lo, float hi) {
    ULL r;
    asm("mov.b64 %0, {%1, %2};" : "=l"(r) : "f"(lo), "f"(hi));
    return r;
}
__device__ __forceinline__ void unpack2(ULL v, float& lo, float& hi) {
    asm("mov.b64 {%0, %1}, %2;" : "=f"(lo), "=f"(hi) : "l"(v));
}
__device__ __forceinline__ void fma2(ULL& d, ULL a, ULL b) {
    asm("fma.rn.f32x2 %0, %1, %2, %0;" : "+l"(d) : "l"(a), "l"(b));
}

// ---------------- accurate activations (immune to fast-math flags) ----------------
// ~1.5-ulp exp for x in [-90, 90]: Cody-Waite reduction + deg-7 Horner + exponent bits.
__device__ __forceinline__ float exp_acc(float x) {
    float z = x * 1.4426950408889634f;
    float n = rintf(z);
    float r = fmaf(n, -0.693147182464599609375f, x);   // x - n*ln2_hi
    r = fmaf(n, 1.9046542121259336e-9f, r);            // - n*ln2_lo
    float p = 1.9841270114e-4f;                         // 1/5040
    p = fmaf(p, r, 1.3888888877e-3f);                   // 1/720
    p = fmaf(p, r, 8.3333337680e-3f);                   // 1/120
    p = fmaf(p, r, 4.1666667908e-2f);                   // 1/24
    p = fmaf(p, r, 1.6666667163e-1f);                   // 1/6
    p = fmaf(p, r, 0.5f);
    p = fmaf(p, r, 1.0f);
    p = fmaf(p, r, 1.0f);
    int i = (int)n;
    float sc = __int_as_float((i + 127) << 23);
    return p * sc;
}

__device__ __forceinline__ float sigm(float x) {
    float xc = fminf(fmaxf(x, -30.0f), 30.0f);
    float s = exp_acc(-xc);
    return __fdiv_rn(1.0f, 1.0f + s);
}

__device__ __forceinline__ float tanh_acc(float x) {
    float ax = fabsf(x);
    float t;
    if (ax < 0.25f) {
        // odd Taylor through x^9: |err| < 3e-9 on this range (no cancellation)
        float x2 = x * x;
        float p = 0.021869488536155203f;                // 62/2835
        p = fmaf(p, x2, -0.05396825396825397f);         // -17/315
        p = fmaf(p, x2, 0.13333333333333333f);          // 2/15
        p = fmaf(p, x2, -0.3333333333333333f);          // -1/3
        p = fmaf(p, x2, 1.0f);
        t = x * p;
    } else {
        float a = fminf(ax, 9.0f);
        float s = exp_acc(-2.0f * a);                   // s in (1.5e-8, 0.6065]
        t = __fdiv_rn(1.0f - s, 1.0f + s);              // no cancellation: 1-s >= 0.39
        t = copysignf(t, x);
    }
    return t;
}

// ---------------- embedding gather (target is int32: jax default x64-disabled) ----------------
__global__ void k_embed(const int* __restrict__ tgt,
                        const float* __restrict__ emb,
                        float* __restrict__ out) {
    int idx = blockIdx.x * blockDim.x + threadIdx.x;
    const int total = 80 * 1024 * 26;
    if (idx < total) {
        int e  = idx % 26;
        int pb = idx / 26;
        int t = tgt[pb] & 63;   // mask: defensive (valid data already in [0,64))
        out[idx] = emb[t * 26 + e];
    }
}

// ---------------- gi GEMM: gi[n][j] = sum_k x[n][k]*Wih[j][k] + bih[j] (+bhh[j] for r,z) ----------------
// Block: 64 rows x 300 cols, 320 threads; thread j owns col j, 64 rows packed as 32 f32x2 accs.
template <int K, int KP, int WS>
__global__ void __launch_bounds__(320) k_gemm(float* __restrict__ gi,
                                              const float* __restrict__ x,
                                              const float* __restrict__ Wih,
                                              const float* __restrict__ bih,
                                              const float* __restrict__ bhh) {
    extern __shared__ float sm[];
    float* Ws = sm;                 // [300][WS]
    float* xs = sm + 300 * WS;      // [KP][66]  (row stride 66 -> 8B-aligned f32x2 reads)
    const int tid = threadIdx.x;

    for (int idx = tid; idx < 300 * WS; idx += 320) {
        int j = idx / WS, k = idx - j * WS;
        Ws[idx] = (k < K) ? Wih[j * K + k] : 0.0f;
    }
    const long n0 = (long)blockIdx.x * 64;
    for (int idx = tid; idx < KP * 64; idx += 320) {
        int r = idx / KP, k = idx - r * KP;
        xs[k * 66 + r] = (k < K) ? x[(n0 + r) * K + k] : 0.0f;
    }
    __syncthreads();

    const int j = tid;
    if (j < 300) {
        float bj = bih[j] + ((j < 200) ? bhh[j] : 0.0f);
        ULL acc[32];
        ULL b2 = pack2(bj, bj);
#pragma unroll
        for (int p = 0; p < 32; p++) acc[p] = b2;

        const float* wrow = Ws + j * WS;
        for (int k4 = 0; k4 < KP / 4; k4++) {
            float4 w4 = *(const float4*)(wrow + k4 * 4);
#pragma unroll
            for (int kk = 0; kk < 4; kk++) {
                float wv = (kk == 0) ? w4.x : (kk == 1) ? w4.y : (kk == 2) ? w4.z : w4.w;
                ULL w2 = pack2(wv, wv);
                const float* xr = xs + (k4 * 4 + kk) * 66;
#pragma unroll
                for (int p = 0; p < 32; p++) {
                    ULL h2 = *(const ULL*)(xr + 2 * p);
                    fma2(acc[p], h2, w2);
                }
            }
        }
        float* gp = gi + n0 * 300 + j;
#pragma unroll
        for (int p = 0; p < 32; p++) {
            float lo, hi;
            unpack2(acc[p], lo, hi);
            gp[(2 * p) * 300]     = lo;
            gp[(2 * p + 1) * 300] = hi;
        }
    }
}

// ---------------- persistent GRU recurrence ----------------
// 128 blocks x 8 batch rows; Whh in smem (stride 108), h in smem [u][8].
// Thread j<300: gate g=j/100, unit u=j%100. Two barriers per step.
__global__ void __launch_bounds__(320) k_gru(const float* __restrict__ gi,
                                             const float* __restrict__ Whh,
                                             const float* __restrict__ bhh,
                                             const float* __restrict__ h0,
                                             float* __restrict__ y,
                                             float* __restrict__ hfin,
                                             int T) {
    extern __shared__ float sm[];
    float* Ws = sm;              // [300][108]
    float* hs = sm + 300 * 108;  // [100][8]
    float* rs = hs + 800;        // [100][8]
    float* zs = rs + 800;        // [100][8]

    const int tid = threadIdx.x;
    const int b0  = blockIdx.x * 8;

    for (int idx = tid; idx < 300 * 108; idx += 320) {
        int jj = idx / 108, k = idx - jj * 108;
        Ws[idx] = (k < 100) ? Whh[jj * 100 + k] : 0.0f;
    }
    for (int idx = tid; idx < 800; idx += 320) {
        int u = idx % 100, r = idx / 100;
        hs[u * 8 + r] = h0 ? h0[(b0 + r) * 100 + u] : 0.0f;
    }

    const int j = tid;
    const int g = (j >= 200) ? 2 : (j >= 100) ? 1 : 0;
    const int u = j - g * 100;
    const float bnn = (j < 300 && g == 2) ? bhh[j] : 0.0f;
    const float* wrow = Ws + j * 108;
    __syncthreads();

    for (int t = 0; t < T; t++) {
        float gv[8], an[8], bn[8];
        if (j < 300) {
            const float* gp = gi + ((long)t * 1024 + b0) * 300 + j;
#pragma unroll
            for (int r = 0; r < 8; r++) gv[r] = gp[r * 300];

            ULL ah[4];
            ULL z2 = pack2(0.0f, 0.0f);
#pragma unroll
            for (int p = 0; p < 4; p++) ah[p] = z2;

            for (int k4 = 0; k4 < 25; k4++) {
                float4 w4 = *(const float4*)(wrow + 4 * k4);
#pragma unroll
                for (int kk = 0; kk < 4; kk++) {
                    float wv = (kk == 0) ? w4.x : (kk == 1) ? w4.y : (kk == 2) ? w4.z : w4.w;
                    ULL w2 = pack2(wv, wv);
                    const ulonglong2* hp = (const ulonglong2*)(hs + (k4 * 4 + kk) * 8);
                    ulonglong2 ha = hp[0];
                    ulonglong2 hb = hp[1];
                    fma2(ah[0], ha.x, w2);
                    fma2(ah[1], ha.y, w2);
                    fma2(ah[2], hb.x, w2);
                    fma2(ah[3], hb.y, w2);
                }
            }
            float ahf[8];
#pragma unroll
            for (int p = 0; p < 4; p++) unpack2(ah[p], ahf[2 * p], ahf[2 * p + 1]);

            if (g == 0) {
#pragma unroll
                for (int r = 0; r < 8; r++) rs[u * 8 + r] = sigm(gv[r] + ahf[r]);
            } else if (g == 1) {
#pragma unroll
                for (int r = 0; r < 8; r++) zs[u * 8 + r] = sigm(gv[r] + ahf[r]);
            } else {
#pragma unroll
                for (int r = 0; r < 8; r++) { an[r] = gv[r]; bn[r] = ahf[r] + bnn; }
            }
        }
        __syncthreads();
        if (j < 300 && g == 2) {
#pragma unroll
            for (int r = 0; r < 8; r++) {
                float rr = rs[u * 8 + r];
                float zz = zs[u * 8 + r];
                float ho = hs[u * 8 + r];
                float nn = tanh_acc(fmaf(rr, bn[r], an[r]));
                float hn = fmaf(zz, ho - nn, nn);   // (1-z)*n + z*h
                hs[u * 8 + r] = hn;
                if (y) y[((long)t * 1024 + b0 + r) * 100 + u] = hn;
                if (hfin && t == T - 1) hfin[(b0 + r) * 100 + u] = hn;
            }
        }
        __syncthreads();
    }
}

// ---------------- logits + argmax + target_cal ----------------
// 16 rows/block, 1024 threads (tid>>6 = row, tid&63 = class).
__global__ void __launch_bounds__(1024) k_out(float* __restrict__ out,
                                              const float* __restrict__ d1,
                                              const float* __restrict__ W,
                                              const float* __restrict__ b,
                                              const int* __restrict__ tgt) {
    __shared__ float Ws[64 * 101];
    __shared__ float ds[16 * 100];
    __shared__ float ls[16 * 64];
    const int tid = threadIdx.x;

    for (int idx = tid; idx < 64 * 101; idx += 1024) {
        int d = idx / 101, k = idx - d * 101;
        Ws[idx] = (k < 100) ? W[d * 100 + k] : 0.0f;
    }
    const long r0 = (long)blockIdx.x * 16;
    for (int idx = tid; idx < 1600; idx += 1024) {
        int rr = idx / 100, k = idx - rr * 100;
        ds[idx] = d1[(r0 + rr) * 100 + k];
    }
    __syncthreads();

    const int rr = tid >> 6;
    const int d  = tid & 63;
    const float* dp = ds + rr * 100;
    const float* wp = Ws + d * 101;
    float a0 = b[d], a1 = 0.0f;
#pragma unroll 2
    for (int k = 0; k < 100; k += 2) {
        a0 = fmaf(dp[k],     wp[k],     a0);
        a1 = fmaf(dp[k + 1], wp[k + 1], a1);
    }
    float acc = a0 + a1;

    const long row = r0 + rr;
    out[row * 64 + d] = acc;
    ls[rr * 64 + d] = acc;
    __syncthreads();

    if (d == 0) {
        float best = ls[rr * 64];
        int bi = 0;
        for (int k = 1; k < 64; k++) {
            float v = ls[rr * 64 + k];
            if (v > best) { best = v; bi = k; }
        }
        out[5177344 + row] = (float)tgt[row + 1024];  // target_cal = target[1:]
        out[5258240 + row] = (float)bi;               // asr_outputs = argmax
    }
}

// ---------------- launch ----------------
extern "C" void kernel_launch(void* const* d_in, const int* in_sizes, int n_in,
                              void* d_out, int out_size) {
    const float* x     = (const float*)d_in[0];
    const int*   tgt   = (const int*)d_in[1];
    const float* emb   = (const float*)d_in[2];
    const float* eWih0 = (const float*)d_in[3];
    const float* eWhh0 = (const float*)d_in[4];
    const float* ebih0 = (const float*)d_in[5];
    const float* ebhh0 = (const float*)d_in[6];
    const float* eWih1 = (const float*)d_in[7];
    const float* eWhh1 = (const float*)d_in[8];
    const float* ebih1 = (const float*)d_in[9];
    const float* ebhh1 = (const float*)d_in[10];
    const float* dWih0 = (const float*)d_in[11];
    const float* dWhh0 = (const float*)d_in[12];
    const float* dbih0 = (const float*)d_in[13];
    const float* dbhh0 = (const float*)d_in[14];
    const float* dWih1 = (const float*)d_in[15];
    const float* dWhh1 = (const float*)d_in[16];
    const float* dbih1 = (const float*)d_in[17];
    const float* dbhh1 = (const float*)d_in[18];
    const float* linW  = (const float*)d_in[19];
    const float* linb  = (const float*)d_in[20];
    float* out = (float*)d_out;

    float *gi, *buf0, *d1b, *decin, *h0b, *h1b;
    cudaGetSymbolAddress((void**)&gi,    g_gi);
    cudaGetSymbolAddress((void**)&buf0,  g_buf0);
    cudaGetSymbolAddress((void**)&d1b,   g_d1);
    cudaGetSymbolAddress((void**)&decin, g_decin);
    cudaGetSymbolAddress((void**)&h0b,   g_h0);
    cudaGetSymbolAddress((void**)&h1b,   g_h1);

    const int SMEM_G26  = (300 * 28 + 28 * 66) * 4;    // 40,992 B
    const int SMEM_G100 = (300 * 108 + 100 * 66) * 4;  // 156,000 B
    const int SMEM_GRU  = (300 * 108 + 3 * 800) * 4;   // 139,200 B
    cudaFuncSetAttribute((const void*)k_gemm<100, 100, 108>,
                         cudaFuncAttributeMaxDynamicSharedMemorySize, SMEM_G100);
    cudaFuncSetAttribute((const void*)k_gru,
                         cudaFuncAttributeMaxDynamicSharedMemorySize, SMEM_GRU);

    // decoder input embedding
    k_embed<<<(80 * 1024 * 26 + 255) / 256, 256>>>(tgt, emb, decin);

    // encoder layer 0
    k_gemm<26, 28, 28><<<8000, 320, SMEM_G26>>>(gi, x, eWih0, ebih0, ebhh0);
    k_gru<<<128, 320, SMEM_GRU>>>(gi, eWhh0, ebhh0, nullptr, buf0, h0b, 500);

    // encoder layer 1 (outputs not needed, only final hidden)
    k_gemm<100, 100, 108><<<8000, 320, SMEM_G100>>>(gi, buf0, eWih1, ebih1, ebhh1);
    k_gru<<<128, 320, SMEM_GRU>>>(gi, eWhh1, ebhh1, nullptr, nullptr, h1b, 500);

    // decoder layer 0
    k_gemm<26, 28, 28><<<1280, 320, SMEM_G26>>>(gi, decin, dWih0, dbih0, dbhh0);
    k_gru<<<128, 320, SMEM_GRU>>>(gi, dWhh0, dbhh0, h0b, buf0, nullptr, 80);

    // decoder layer 1
    k_gemm<100, 100, 108><<<1280, 320, SMEM_G100>>>(gi, buf0, dWih1, dbih1, dbhh1);
    k_gru<<<128, 320, SMEM_GRU>>>(gi, dWhh1, dbhh1, h1b, d1b, nullptr, 80);

    // logits + outputs (79*1024 rows, 16 rows/block)
    k_out<<<5056, 1024>>>(out, d1b, linW, linb, tgt);
}

// round 6
// speedup vs baseline: 1.8932x; 1.8932x over previous
#include <cuda_runtime.h>

typedef unsigned long long ULL;

// ---------------- scratch (static device globals; no allocation) ----------------
static __device__ float g_gi[500 * 1024 * 300];     // 614.4 MB: gi for current layer
static __device__ float g_buf0[500 * 1024 * 100];   // 204.8 MB: e0 / d0 sequence
static __device__ float g_d1[80 * 1024 * 100];      // decoder layer-1 outputs
static __device__ float g_decin[80 * 1024 * 26];    // embedded decoder inputs
static __device__ float g_h0[1024 * 100];           // h_enc0
static __device__ float g_h1[1024 * 100];           // h_enc1

// ---------------- f32x2 helpers ----------------
__device__ __forceinline__ ULL pack2(float lo, float hi) {
    ULL r;
    asm("mov.b64 %0, {%1, %2};" : "=l"(r) : "f"(lo), "f"(hi));
    return r;
}
__device__ __forceinline__ void unpack2(ULL v, float& lo, float& hi) {
    asm("mov.b64 {%0, %1}, %2;" : "=f"(lo), "=f"(hi) : "l"(v));
}
__device__ __forceinline__ void fma2(ULL& d, ULL a, ULL b) {
    asm("fma.rn.f32x2 %0, %1, %2, %0;" : "+l"(d) : "l"(a), "l"(b));
}

// ---------------- accurate activations (immune to fast-math flags) ----------------
__device__ __forceinline__ float exp_acc(float x) {
    float z = x * 1.4426950408889634f;
    float n = rintf(z);
    float r = fmaf(n, -0.693147182464599609375f, x);
    r = fmaf(n, 1.9046542121259336e-9f, r);
    float p = 1.9841270114e-4f;
    p = fmaf(p, r, 1.3888888877e-3f);
    p = fmaf(p, r, 8.3333337680e-3f);
    p = fmaf(p, r, 4.1666667908e-2f);
    p = fmaf(p, r, 1.6666667163e-1f);
    p = fmaf(p, r, 0.5f);
    p = fmaf(p, r, 1.0f);
    p = fmaf(p, r, 1.0f);
    int i = (int)n;
    float sc = __int_as_float((i + 127) << 23);
    return p * sc;
}
__device__ __forceinline__ float sigm(float x) {
    float xc = fminf(fmaxf(x, -30.0f), 30.0f);
    float s = exp_acc(-xc);
    return __fdiv_rn(1.0f, 1.0f + s);
}
__device__ __forceinline__ float tanh_acc(float x) {
    float ax = fabsf(x);
    float t;
    if (ax < 0.25f) {
        float x2 = x * x;
        float p = 0.021869488536155203f;
        p = fmaf(p, x2, -0.05396825396825397f);
        p = fmaf(p, x2, 0.13333333333333333f);
        p = fmaf(p, x2, -0.3333333333333333f);
        p = fmaf(p, x2, 1.0f);
        t = x * p;
    } else {
        float a = fminf(ax, 9.0f);
        float s = exp_acc(-2.0f * a);
        t = __fdiv_rn(1.0f - s, 1.0f + s);
        t = copysignf(t, x);
    }
    return t;
}

// ---------------- embedding gather ----------------
__global__ void k_embed(const int* __restrict__ tgt,
                        const float* __restrict__ emb,
                        float* __restrict__ out) {
    int idx = blockIdx.x * blockDim.x + threadIdx.x;
    const int total = 80 * 1024 * 26;
    if (idx < total) {
        int e  = idx % 26;
        int pb = idx / 26;
        int t = tgt[pb] & 63;
        out[idx] = emb[t * 26 + e];
    }
}

// ---------------- gi GEMM (2D register tile; bitwise: bias + k-ascending chain) ----------------
// Tile M=128 x N=64, 256 threads; thread-tile 8 rows x 4 cols.
template <int K>
__global__ void __launch_bounds__(256) k_gemm(float* __restrict__ gi,
                                              const float* __restrict__ x,
                                              const float* __restrict__ W,
                                              const float* __restrict__ bih,
                                              const float* __restrict__ bhh) {
    const int MP = 132;   // A smem stride (floats)
    const int BP = 68;    // B smem stride
    extern __shared__ float sm[];
    float* As = sm;              // [K][132]  (k-major)
    float* Bs = sm + K * MP;     // [K][68]

    const int tid = threadIdx.x;
    const long n0 = (long)blockIdx.x * 128;
    const int  j0 = blockIdx.y * 64;

    for (int idx = tid; idx < 128 * K; idx += 256) {
        int m = idx / K, k = idx - m * K;
        As[k * MP + m] = x[(n0 + m) * K + k];
    }
    for (int idx = tid; idx < 64 * K; idx += 256) {
        int jj = idx / K, k = idx - jj * K;
        int j = j0 + jj;
        Bs[k * BP + jj] = (j < 300) ? W[j * K + k] : 0.0f;
    }
    __syncthreads();

    const int cx = tid & 15;      // 16 col-groups * 4 cols = 64
    const int ry = tid >> 4;      // 16 row-groups * 8 rows = 128

    ULL acc[4][4];
#pragma unroll
    for (int c = 0; c < 4; c++) {
        int j = j0 + cx * 4 + c;
        float bj = 0.0f;
        if (j < 300) bj = bih[j] + ((j < 200) ? bhh[j] : 0.0f);
        ULL b2 = pack2(bj, bj);
#pragma unroll
        for (int rp = 0; rp < 4; rp++) acc[c][rp] = b2;
    }

    const float* abase = As + ry * 8;
    const float* bbase = Bs + cx * 4;
#pragma unroll 2
    for (int k = 0; k < K; k++) {
        ulonglong2 a01 = *(const ulonglong2*)(abase + k * MP);
        ulonglong2 a23 = *(const ulonglong2*)(abase + k * MP + 4);
        float4 b4 = *(const float4*)(bbase + k * BP);
#pragma unroll
        for (int c = 0; c < 4; c++) {
            float bc = (c == 0) ? b4.x : (c == 1) ? b4.y : (c == 2) ? b4.z : b4.w;
            ULL w2 = pack2(bc, bc);
            fma2(acc[c][0], a01.x, w2);
            fma2(acc[c][1], a01.y, w2);
            fma2(acc[c][2], a23.x, w2);
            fma2(acc[c][3], a23.y, w2);
        }
    }

    if (j0 + cx * 4 < 300) {
        float v[4][8];
#pragma unroll
        for (int c = 0; c < 4; c++)
#pragma unroll
            for (int rp = 0; rp < 4; rp++)
                unpack2(acc[c][rp], v[c][2 * rp], v[c][2 * rp + 1]);
#pragma unroll
        for (int r = 0; r < 8; r++) {
            float4 f;
            f.x = v[0][r]; f.y = v[1][r]; f.z = v[2][r]; f.w = v[3][r];
            *(float4*)(gi + (n0 + ry * 8 + r) * 300 + j0 + cx * 4) = f;
        }
    }
}

// ---------------- persistent GRU recurrence ----------------
// 128 blocks x 8 batch rows; 608 threads (600 active): thread = (j, rh), rows rh*4..rh*4+3.
// BITWISE round-4 semantics: f32x2 lanes = row pairs, each row's chain is k-ascending from 0.
// hs layout [k][8] (rows contiguous) -> 1 LDS.128 gives rows rh*4..+3 for one k.
__global__ void __launch_bounds__(608) k_gru(const float* __restrict__ gi,
                                             const float* __restrict__ Whh,
                                             const float* __restrict__ bhh,
                                             const float* __restrict__ h0,
                                             float* __restrict__ y,
                                             float* __restrict__ hfin,
                                             int T) {
    const int WP = 108;   // Ws row stride
    extern __shared__ float sm[];
    float* Ws = sm;                   // [300][108]
    float* hs = sm + 300 * WP;        // [100][8]: hs[k*8 + row]
    float* rs = hs + 800;             // [100][12]: rs[u*12 + rh*4 + r]
    float* zs = rs + 100 * 12;        // [100][12]

    const int tid = threadIdx.x;
    const int b0  = blockIdx.x * 8;
    const bool active = tid < 600;
    const int j  = active ? (tid % 300) : 0;
    const int rh = active ? (tid / 300) : 0;
    const int g  = (j >= 200) ? 2 : (j >= 100) ? 1 : 0;
    const int u  = j - g * 100;

    for (int idx = tid; idx < 300 * WP; idx += 608) {
        int jj = idx / WP, k = idx - jj * WP;
        Ws[idx] = (k < 100) ? Whh[jj * 100 + k] : 0.0f;
    }
    for (int idx = tid; idx < 800; idx += 608) {
        int r = idx & 7, k = idx >> 3;
        hs[idx] = h0 ? h0[(b0 + r) * 100 + k] : 0.0f;
    }
    const float bnn = (active && g == 2) ? bhh[j] : 0.0f;
    const float* wrow = Ws + j * WP;
    const float* hbase = hs + rh * 4;
    __syncthreads();

    for (int t = 0; t < T; t++) {
        float gv[4], an[4], bn[4];
        if (active) {
            const float* gp = gi + ((long)t * 1024 + b0 + rh * 4) * 300 + j;
#pragma unroll
            for (int r = 0; r < 4; r++) gv[r] = gp[r * 300];

            // lanes = row pairs (rh*4+0, rh*4+1) and (rh*4+2, rh*4+3); k-ascending chains
            ULL a01 = 0, a23 = 0;
#pragma unroll 5
            for (int k4 = 0; k4 < 25; k4++) {
                float4 w4 = *(const float4*)(wrow + k4 * 4);
#pragma unroll
                for (int kk = 0; kk < 4; kk++) {
                    float wv = (kk == 0) ? w4.x : (kk == 1) ? w4.y : (kk == 2) ? w4.z : w4.w;
                    ULL w2 = pack2(wv, wv);
                    ulonglong2 hv = *(const ulonglong2*)(hbase + (k4 * 4 + kk) * 8);
                    fma2(a01, hv.x, w2);
                    fma2(a23, hv.y, w2);
                }
            }
            float ah[4];
            unpack2(a01, ah[0], ah[1]);
            unpack2(a23, ah[2], ah[3]);

            if (g == 0) {
#pragma unroll
                for (int r = 0; r < 4; r++) rs[u * 12 + rh * 4 + r] = sigm(gv[r] + ah[r]);
            } else if (g == 1) {
#pragma unroll
                for (int r = 0; r < 4; r++) zs[u * 12 + rh * 4 + r] = sigm(gv[r] + ah[r]);
            } else {
#pragma unroll
                for (int r = 0; r < 4; r++) { an[r] = gv[r]; bn[r] = ah[r] + bnn; }
            }
        }
        __syncthreads();
        if (active && g == 2) {
            float4 rv = *(const float4*)(rs + u * 12 + rh * 4);
            float4 zv = *(const float4*)(zs + u * 12 + rh * 4);
#pragma unroll
            for (int r = 0; r < 4; r++) {
                float rr = (r == 0) ? rv.x : (r == 1) ? rv.y : (r == 2) ? rv.z : rv.w;
                float zz = (r == 0) ? zv.x : (r == 1) ? zv.y : (r == 2) ? zv.z : zv.w;
                int row = rh * 4 + r;
                float ho = hs[u * 8 + row];
                float nn = tanh_acc(fmaf(rr, bn[r], an[r]));
                float hn = fmaf(zz, ho - nn, nn);
                hs[u * 8 + row] = hn;
                if (y) y[((long)t * 1024 + b0 + row) * 100 + u] = hn;
                if (hfin && t == T - 1) hfin[(b0 + row) * 100 + u] = hn;
            }
        }
        __syncthreads();
    }
}

// ---------------- logits + argmax + target_cal ----------------
__global__ void __launch_bounds__(1024) k_out(float* __restrict__ out,
                                              const float* __restrict__ d1,
                                              const float* __restrict__ W,
                                              const float* __restrict__ b,
                                              const int* __restrict__ tgt) {
    __shared__ float Ws[64 * 101];
    __shared__ float ds[16 * 100];
    __shared__ float ls[16 * 64];
    const int tid = threadIdx.x;

    for (int idx = tid; idx < 64 * 101; idx += 1024) {
        int d = idx / 101, k = idx - d * 101;
        Ws[idx] = (k < 100) ? W[d * 100 + k] : 0.0f;
    }
    const long r0 = (long)blockIdx.x * 16;
    for (int idx = tid; idx < 1600; idx += 1024) {
        int rr = idx / 100, k = idx - rr * 100;
        ds[idx] = d1[(r0 + rr) * 100 + k];
    }
    __syncthreads();

    const int rr = tid >> 6;
    const int d  = tid & 63;
    const float* dp = ds + rr * 100;
    const float* wp = Ws + d * 101;
    float a0 = b[d], a1 = 0.0f;
#pragma unroll 2
    for (int k = 0; k < 100; k += 2) {
        a0 = fmaf(dp[k],     wp[k],     a0);
        a1 = fmaf(dp[k + 1], wp[k + 1], a1);
    }
    float acc = a0 + a1;

    const long row = r0 + rr;
    out[row * 64 + d] = acc;
    ls[rr * 64 + d] = acc;
    __syncthreads();

    if (d == 0) {
        float best = ls[rr * 64];
        int bi = 0;
        for (int k = 1; k < 64; k++) {
            float v = ls[rr * 64 + k];
            if (v > best) { best = v; bi = k; }
        }
        out[5177344 + row] = (float)tgt[row + 1024];
        out[5258240 + row] = (float)bi;
    }
}

// ---------------- launch ----------------
extern "C" void kernel_launch(void* const* d_in, const int* in_sizes, int n_in,
                              void* d_out, int out_size) {
    const float* x     = (const float*)d_in[0];
    const int*   tgt   = (const int*)d_in[1];
    const float* emb   = (const float*)d_in[2];
    const float* eWih0 = (const float*)d_in[3];
    const float* eWhh0 = (const float*)d_in[4];
    const float* ebih0 = (const float*)d_in[5];
    const float* ebhh0 = (const float*)d_in[6];
    const float* eWih1 = (const float*)d_in[7];
    const float* eWhh1 = (const float*)d_in[8];
    const float* ebih1 = (const float*)d_in[9];
    const float* ebhh1 = (const float*)d_in[10];
    const float* dWih0 = (const float*)d_in[11];
    const float* dWhh0 = (const float*)d_in[12];
    const float* dbih0 = (const float*)d_in[13];
    const float* dbhh0 = (const float*)d_in[14];
    const float* dWih1 = (const float*)d_in[15];
    const float* dWhh1 = (const float*)d_in[16];
    const float* dbih1 = (const float*)d_in[17];
    const float* dbhh1 = (const float*)d_in[18];
    const float* linW  = (const float*)d_in[19];
    const float* linb  = (const float*)d_in[20];
    float* out = (float*)d_out;

    float *gi, *buf0, *d1b, *decin, *h0b, *h1b;
    cudaGetSymbolAddress((void**)&gi,    g_gi);
    cudaGetSymbolAddress((void**)&buf0,  g_buf0);
    cudaGetSymbolAddress((void**)&d1b,   g_d1);
    cudaGetSymbolAddress((void**)&decin, g_decin);
    cudaGetSymbolAddress((void**)&h0b,   g_h0);
    cudaGetSymbolAddress((void**)&h1b,   g_h1);

    const int SMEM_G26  = (26 * 132 + 26 * 68) * 4;     // 20,800 B
    const int SMEM_G100 = (100 * 132 + 100 * 68) * 4;   // 80,000 B
    const int SMEM_GRU  = (300 * 108 + 800 + 2 * 1200) * 4;  // 142,400 B
    cudaFuncSetAttribute((const void*)k_gemm<26>,
                         cudaFuncAttributeMaxDynamicSharedMemorySize, SMEM_G26);
    cudaFuncSetAttribute((const void*)k_gemm<100>,
                         cudaFuncAttributeMaxDynamicSharedMemorySize, SMEM_G100);
    cudaFuncSetAttribute((const void*)k_gru,
                         cudaFuncAttributeMaxDynamicSharedMemorySize, SMEM_GRU);

    // decoder input embedding
    k_embed<<<(80 * 1024 * 26 + 255) / 256, 256>>>(tgt, emb, decin);

    // encoder layer 0
    k_gemm<26><<<dim3(4000, 5), 256, SMEM_G26>>>(gi, x, eWih0, ebih0, ebhh0);
    k_gru<<<128, 608, SMEM_GRU>>>(gi, eWhh0, ebhh0, nullptr, buf0, h0b, 500);

    // encoder layer 1 (only final hidden needed)
    k_gemm<100><<<dim3(4000, 5), 256, SMEM_G100>>>(gi, buf0, eWih1, ebih1, ebhh1);
    k_gru<<<128, 608, SMEM_GRU>>>(gi, eWhh1, ebhh1, nullptr, nullptr, h1b, 500);

    // decoder layer 0
    k_gemm<26><<<dim3(640, 5), 256, SMEM_G26>>>(gi, decin, dWih0, dbih0, dbhh0);
    k_gru<<<128, 608, SMEM_GRU>>>(gi, dWhh0, dbhh0, h0b, buf0, nullptr, 80);

    // decoder layer 1
    k_gemm<100><<<dim3(640, 5), 256, SMEM_G100>>>(gi, buf0, dWih1, dbih1, dbhh1);
    k_gru<<<128, 608, SMEM_GRU>>>(gi, dWhh1, dbhh1, h1b, d1b, nullptr, 80);

    // logits + outputs
    k_out<<<5056, 1024>>>(out, d1b, linW, linb, tgt);
}